// round 9
// baseline (speedup 1.0000x reference)
#include <cuda_runtime.h>
#include <math.h>

// Cox partial likelihood, single fused kernel (v9):
//   Phase 1 (per CTA = one chunk of 256): warp-shuffle bitonic sort of packed
//     (key(T)<<32|idx); e=exp(theta) gathered post-sort; suffix sums via
//     shuffle scan -> g_u/g_sfx/g_idx.  Release + ticket.
//   Grid "barrier": tid0 spins on ticket (grid=64 < 148 SMs => co-resident).
//   Phase 2: stage ALL 64 chunk key tables (64KB) in SMEM; each thread ranks
//     its own slot key against all chunks (depth-8 searches, ILP=4); suffix
//     values fetched from L2. rss complete locally -> loss term.
//   Phase 3: block reduce -> g_loss[c]; last CTA reduces 64 floats -> out,
//     resets tickets (graph-replay safe).

#define NN  16384
#define CH  256
#define NCH 64                    // NN / CH ; co-resident grid

typedef unsigned long long ull;

__device__ unsigned g_u  [NN];               // sorted keys, chunk-major
__device__ float    g_sfx[NCH * (CH + 1)];   // suffix sums (+0 sentinel)
__device__ float    g_loss[NCH];             // per-CTA loss partials
__device__ unsigned g_t1, g_t2;              // phase tickets (zero-init, self-reset)

__device__ __forceinline__ unsigned key_of(float t) {
    unsigned b = __float_as_uint(t);
    return b ^ ((unsigned)((int)b >> 31) | 0x80000000u);   // never 0 for finite t
}

extern "C" __global__ void __launch_bounds__(CH)
fused_kernel(const float* __restrict__ theta, const float* __restrict__ T,
             const float* __restrict__ ev, int n, float* __restrict__ out) {
    extern __shared__ char smem[];
    ull* sbuf = (ull*)smem;                       // phase 1: [2][CH] = 4KB
    unsigned* ck = (unsigned*)smem;               // phase 2: [NCH][CH] = 64KB

    __shared__ float swarp[CH / 32];
    __shared__ float soff [CH / 32];
    __shared__ float wsum [CH / 32];

    const int c    = blockIdx.x;
    const int t    = threadIdx.x;
    const int lane = t & 31;
    const int w    = t >> 5;
    const int j    = c * CH + t;

    // ---------------- Phase 1: sort own chunk ----------------
    ull kv = (j < n) ? (((ull)key_of(T[j]) << 32) | (unsigned)j) : 0ull;
    int buf = 0;
    for (int k = 2; k <= CH; k <<= 1) {
        for (int s = k >> 1; s > 0; s >>= 1) {
            const bool keep_min = (((t & s) == 0) == ((t & k) == 0));
            ull pkv;
            if (s >= 32) {
                sbuf[buf * CH + t] = kv;
                __syncthreads();
                pkv = sbuf[buf * CH + (t ^ s)];
                buf ^= 1;                        // next SMEM substage: other buffer
            } else {
                pkv = __shfl_xor_sync(0xFFFFFFFFu, kv, s);
            }
            const bool take = keep_min ? (pkv < kv) : (pkv > kv);
            if (take) kv = pkv;
        }
    }

    const unsigned u   = (unsigned)(kv >> 32);   // my slot key (stays in reg)
    const int      idx = (int)(unsigned)kv;      // my slot's original index
    const float    e   = (idx < n) ? expf(theta[idx]) : 0.0f;

    // inclusive suffix sum of e over sorted positions
    float ssum = e;
#pragma unroll
    for (int off = 1; off < 32; off <<= 1) {
        float v = __shfl_down_sync(0xFFFFFFFFu, ssum, off);
        if (lane + off < 32) ssum += v;
    }
    if (lane == 0) swarp[w] = ssum;
    __syncthreads();
    if (t < CH / 32) {
        float v = swarp[t];
#pragma unroll
        for (int off = 1; off < CH / 32; off <<= 1) {
            float x = __shfl_down_sync(0xFFu, v, off);
            if (t + off < CH / 32) v += x;
        }
        soff[t] = v - swarp[t];
    }
    __syncthreads();

    g_u  [c * CH + t]       = u;
    g_sfx[c * (CH + 1) + t] = ssum + soff[w];
    if (t == 0) g_sfx[c * (CH + 1) + CH] = 0.0f;

    // ---- release + grid barrier (one fence/atomic per CTA) ----
    __syncthreads();
    if (t == 0) {
        __threadfence();                          // publish sorted tables
        atomicAdd(&g_t1, 1u);
        while (*(volatile unsigned*)&g_t1 < NCH) {}
        __threadfence();                          // acquire all CTAs' tables
    }
    __syncthreads();

    // ---------------- Phase 2: rank against all chunks ----------------
    for (int i = t; i < NN; i += CH) ck[i] = g_u[i];   // 64KB stage (overwrites sbuf)
    __syncthreads();

    float rss = 0.0f;
#pragma unroll 1
    for (int cc = 0; cc < NCH; cc += 4) {        // 4 independent search chains
        const unsigned* A0 = ck + (cc + 0) * CH;
        const unsigned* A1 = ck + (cc + 1) * CH;
        const unsigned* A2 = ck + (cc + 2) * CH;
        const unsigned* A3 = ck + (cc + 3) * CH;
        int l0 = 0, l1 = 0, l2 = 0, l3 = 0;
#pragma unroll
        for (int s = CH / 2; s > 0; s >>= 1) {
            if (A0[l0 + s - 1] < u) l0 += s;
            if (A1[l1 + s - 1] < u) l1 += s;
            if (A2[l2 + s - 1] < u) l2 += s;
            if (A3[l3 + s - 1] < u) l3 += s;
        }
        rss += __ldg(g_sfx + (cc + 0) * (CH + 1) + l0)
             + __ldg(g_sfx + (cc + 1) * (CH + 1) + l1)
             + __ldg(g_sfx + (cc + 2) * (CH + 1) + l2)
             + __ldg(g_sfx + (cc + 3) * (CH + 1) + l3);
    }

    float term = (j < n) ? (theta[idx] - logf(rss)) * ev[idx] : 0.0f;

    // ---------------- Phase 3: reduce ----------------
    for (int off = 16; off > 0; off >>= 1)
        term += __shfl_down_sync(0xFFFFFFFFu, term, off);
    if (lane == 0) wsum[w] = term;
    __syncthreads();
    if (t == 0) {
        float bs = 0.0f;
#pragma unroll
        for (int ww = 0; ww < CH / 32; ww++) bs += wsum[ww];
        g_loss[c] = bs;
        __threadfence();
        unsigned tk = atomicAdd(&g_t2, 1u);
        if (tk == NCH - 1) {                      // last CTA finalizes
            __threadfence();
            float s = 0.0f;
#pragma unroll
            for (int i = 0; i < NCH; i++) s += g_loss[i];
            out[0] = -s / (float)n;
            g_t1 = 0;                             // reset for next replay
            g_t2 = 0;
        }
    }
}

extern "C" void kernel_launch(void* const* d_in, const int* in_sizes, int n_in,
                              void* d_out, int out_size) {
    const float* theta = (const float*)d_in[0];
    const float* T     = (const float*)d_in[1];
    const float* ev    = (const float*)d_in[2];
    float*       out   = (float*)d_out;
    const int n = in_sizes[0];

    static int smem_set = 0;
    const int smem_bytes = NN * (int)sizeof(unsigned);   // 64KB
    if (!smem_set) {
        cudaFuncSetAttribute(fused_kernel,
                             cudaFuncAttributeMaxDynamicSharedMemorySize,
                             smem_bytes);
        smem_set = 1;
    }
    fused_kernel<<<NCH, CH, smem_bytes>>>(theta, T, ev, n, out);
}

// round 10
// speedup vs baseline: 1.0343x; 1.0343x over previous
#include <cuda_runtime.h>
#include <math.h>

// Cox partial likelihood, single fused kernel (v10):
//   Grid = 128 CTAs x 256 thr (co-resident on 148 SMs -> ticket grid barriers).
//   Phase 1 (CTAs 0..63): count-rank sort of chunk c (256 packed keys in SMEM,
//     each thread counts kv_j < kv_i -> rank), scatter key/idx/e, suffix-scan e.
//   Barrier 1 (64 arrivals).
//   Phase 2 (all 128 CTAs): CTA (tile, half) stages 32 chunk key-tables (32KB),
//     binary-searches its tile's 256 slot keys (ILP-4), sfx gathered from L2,
//     partial rss -> plain store g_part[half][slot].
//   Barrier 2 (128 arrivals).
//   Phase 3: CTA b computes loss terms for slots [b*128, b*128+128), block
//     reduce -> g_loss[b]; last CTA (ticket) sums 128 floats -> out, resets.

#define NN    16384
#define CH    256
#define NCH   64
#define GRID  128
#define TPB   256
#define HCH   32                 // chunks per phase-2 CTA

typedef unsigned long long ull;

__device__ unsigned g_u  [NN];               // sorted keys, chunk-major
__device__ float    g_sfx[NCH * (CH + 1)];   // suffix sums (+0 sentinel)
__device__ int      g_idx[NN];               // original index per sorted slot
__device__ float    g_part[2 * NN];          // per-half partial rss
__device__ float    g_loss[GRID];            // per-CTA loss partials
__device__ unsigned g_b1, g_b2, g_b3;        // tickets (zero-init, self-reset)

__device__ __forceinline__ unsigned key_of(float t) {
    unsigned b = __float_as_uint(t);
    return b ^ ((unsigned)((int)b >> 31) | 0x80000000u);
}

extern "C" __global__ void __launch_bounds__(TPB)
fused_kernel(const float* __restrict__ theta, const float* __restrict__ T,
             const float* __restrict__ ev, int n, float* __restrict__ out) {
    __shared__ ull      skv[CH];             // phase 1 keys       (2KB)
    __shared__ unsigned ck [HCH * CH];       // phase 2 key tables (32KB)
    __shared__ float    se [CH];             // phase 1 e, sorted  (1KB)
    __shared__ float    swarp[CH / 32];
    __shared__ float    soff [CH / 32];
    __shared__ float    wsum [CH / 32];

    const int b    = blockIdx.x;
    const int t    = threadIdx.x;
    const int lane = t & 31;
    const int w    = t >> 5;

    // ---------------- Phase 1: count-rank sort (CTAs 0..NCH-1) ----------------
    if (b < NCH) {
        const int j = b * CH + t;
        const float e  = (j < n) ? expf(theta[j]) : 0.0f;     // early: hide MUFU+LDG
        const ull   kv = (j < n) ? (((ull)key_of(T[j]) << 32) | (unsigned)j) : (ull)t;
        skv[t] = kv;
        __syncthreads();

        // rank = #{ m : skv[m] < kv }  (unique keys -> permutation)
        int rank = 0;
        const ulonglong2* p2 = (const ulonglong2*)skv;
#pragma unroll 8
        for (int m = 0; m < CH / 2; m++) {
            ulonglong2 v = p2[m];               // broadcast LDS.128
            rank += (v.x < kv) + (v.y < kv);
        }

        g_u  [b * CH + rank] = (unsigned)(kv >> 32);
        g_idx[b * CH + rank] = (int)(unsigned)kv;
        se[rank] = e;
        __syncthreads();

        // inclusive suffix sum of se over sorted positions
        float ssum = se[t];
#pragma unroll
        for (int off = 1; off < 32; off <<= 1) {
            float v = __shfl_down_sync(0xFFFFFFFFu, ssum, off);
            if (lane + off < 32) ssum += v;
        }
        if (lane == 0) swarp[w] = ssum;
        __syncthreads();
        if (t < CH / 32) {
            float v = swarp[t];
#pragma unroll
            for (int off = 1; off < CH / 32; off <<= 1) {
                float x = __shfl_down_sync(0xFFu, v, off);
                if (t + off < CH / 32) v += x;
            }
            soff[t] = v - swarp[t];
        }
        __syncthreads();

        g_sfx[b * (CH + 1) + t] = ssum + soff[w];
        if (t == 0) g_sfx[b * (CH + 1) + CH] = 0.0f;
        __syncthreads();
    }

    // ---------------- Barrier 1: all sorted tables published ----------------
    if (t == 0) {
        if (b < NCH) { __threadfence(); atomicAdd(&g_b1, 1u); }
        while (*(volatile unsigned*)&g_b1 < (unsigned)NCH) {}
        __threadfence();
    }
    __syncthreads();

    // ---------------- Phase 2: rank tile against half the chunks ----------------
    const int tile = b >> 1;
    const int half = b & 1;
    const int cbase = half * HCH;            // first chunk of this half

    for (int i = t; i < HCH * CH; i += TPB) ck[i] = g_u[cbase * CH + i];
    const unsigned u = g_u[tile * CH + t];   // my slot key
    __syncthreads();

    float rss = 0.0f;
#pragma unroll 1
    for (int cc = 0; cc < HCH; cc += 4) {    // 4 independent search chains
        const unsigned* A0 = ck + (cc + 0) * CH;
        const unsigned* A1 = ck + (cc + 1) * CH;
        const unsigned* A2 = ck + (cc + 2) * CH;
        const unsigned* A3 = ck + (cc + 3) * CH;
        int l0 = 0, l1 = 0, l2 = 0, l3 = 0;
#pragma unroll
        for (int s = CH / 2; s > 0; s >>= 1) {
            if (A0[l0 + s - 1] < u) l0 += s;
            if (A1[l1 + s - 1] < u) l1 += s;
            if (A2[l2 + s - 1] < u) l2 += s;
            if (A3[l3 + s - 1] < u) l3 += s;
        }
        rss += __ldg(g_sfx + (cbase + cc + 0) * (CH + 1) + l0)
             + __ldg(g_sfx + (cbase + cc + 1) * (CH + 1) + l1)
             + __ldg(g_sfx + (cbase + cc + 2) * (CH + 1) + l2)
             + __ldg(g_sfx + (cbase + cc + 3) * (CH + 1) + l3);
    }
    g_part[half * NN + tile * CH + t] = rss;

    // ---------------- Barrier 2: all partials published ----------------
    if (t == 0) {
        __threadfence();
        atomicAdd(&g_b2, 1u);
        while (*(volatile unsigned*)&g_b2 < (unsigned)GRID) {}
        __threadfence();
    }
    __syncthreads();

    // ---------------- Phase 3: loss for slots [b*128, b*128+128) ----------------
    float term = 0.0f;
    if (t < NN / GRID) {
        const int s = b * (NN / GRID) + t;
        const float r = *((volatile float*)g_part + s)
                      + *((volatile float*)g_part + NN + s);
        const int io = g_idx[s];
        term = (theta[io] - logf(r)) * ev[io];
    }

    for (int off = 16; off > 0; off >>= 1)
        term += __shfl_down_sync(0xFFFFFFFFu, term, off);
    if (lane == 0) wsum[w] = term;
    __syncthreads();

    if (t == 0) {
        float bs = 0.0f;
#pragma unroll
        for (int ww = 0; ww < CH / 32; ww++) bs += wsum[ww];
        g_loss[b] = bs;
        __threadfence();
        unsigned tk = atomicAdd(&g_b3, 1u);
        if (tk == GRID - 1) {                 // last CTA finalizes
            __threadfence();
            float s = 0.0f;
            for (int i = 0; i < GRID; i++) s += *((volatile float*)g_loss + i);
            out[0] = -s / (float)n;
            g_b1 = 0;  g_b2 = 0;  g_b3 = 0;   // reset for next replay
        }
    }
}

extern "C" void kernel_launch(void* const* d_in, const int* in_sizes, int n_in,
                              void* d_out, int out_size) {
    const float* theta = (const float*)d_in[0];
    const float* T     = (const float*)d_in[1];
    const float* ev    = (const float*)d_in[2];
    float*       out   = (float*)d_out;
    const int n = in_sizes[0];

    fused_kernel<<<GRID, TPB>>>(theta, T, ev, n, out);
}

// round 11
// speedup vs baseline: 1.1087x; 1.0719x over previous
#include <cuda_runtime.h>
#include <math.h>

// Cox partial likelihood, 2 kernels (v11):
//   K1 (64 CTAs x 256): count-rank sort per chunk of 256 — stage packed
//     (key(T)<<32|idx) in SMEM, rank_i = #{kv_m < kv_i} (broadcast LDS.128),
//     scatter key/idx/e, shuffle suffix-scan of e -> g_u/g_idx/g_sfx. Zeros out.
//   K2 (128 CTAs x 256): stage ALL 64 chunk key tables (64KB SMEM); 2 threads
//     per slot, each searches 32 chunks (depth-8, ILP-4), sfx from L2; halves
//     combined in SMEM; loss terms block-reduced; one atomicAdd(out) per CTA.

#define NN    16384
#define CH    256
#define NCH   64                 // NN / CH
#define RTILE 128                // slots per K2 CTA
#define K2G   (NN / RTILE)       // 128 CTAs
#define HCH   (NCH / 2)          // 32 chunks per thread-half

typedef unsigned long long ull;

__device__ unsigned g_u  [NN];               // sorted keys, chunk-major
__device__ float    g_sfx[NCH * (CH + 1)];   // suffix sums (+0 sentinel)
__device__ int      g_idx[NN];               // original index per sorted slot

__device__ __forceinline__ unsigned key_of(float t) {
    unsigned b = __float_as_uint(t);
    return b ^ ((unsigned)((int)b >> 31) | 0x80000000u);   // never 0 for finite t
}

__global__ void __launch_bounds__(CH)
sort_kernel(const float* __restrict__ theta, const float* __restrict__ T,
            int n, float* __restrict__ out) {
    __shared__ ull   skv[CH];
    __shared__ float se [CH];
    __shared__ float swarp[CH / 32];
    __shared__ float soff [CH / 32];

    const int c    = blockIdx.x;
    const int t    = threadIdx.x;
    const int lane = t & 31;
    const int w    = t >> 5;
    const int j    = c * CH + t;

    const float e  = (j < n) ? expf(theta[j]) : 0.0f;
    const ull   kv = (j < n) ? (((ull)key_of(T[j]) << 32) | (unsigned)j) : (ull)t;
    skv[t] = kv;
    __syncthreads();

    // rank = #{ m : skv[m] < kv }  (keys unique via idx low bits)
    int rank = 0;
    const ulonglong2* p2 = (const ulonglong2*)skv;
#pragma unroll 8
    for (int m = 0; m < CH / 2; m++) {
        ulonglong2 v = p2[m];                 // broadcast LDS.128
        rank += (v.x < kv) + (v.y < kv);
    }

    g_u  [c * CH + rank] = (unsigned)(kv >> 32);
    g_idx[c * CH + rank] = (int)(unsigned)kv;
    se[rank] = e;
    __syncthreads();

    // inclusive suffix sum of se over sorted positions
    float ssum = se[t];
#pragma unroll
    for (int off = 1; off < 32; off <<= 1) {
        float v = __shfl_down_sync(0xFFFFFFFFu, ssum, off);
        if (lane + off < 32) ssum += v;
    }
    if (lane == 0) swarp[w] = ssum;
    __syncthreads();
    if (t < CH / 32) {                        // 8 warp totals -> exclusive suffix
        float v = swarp[t];
#pragma unroll
        for (int off = 1; off < CH / 32; off <<= 1) {
            float x = __shfl_down_sync(0xFFu, v, off);
            if (t + off < CH / 32) v += x;
        }
        soff[t] = v - swarp[t];
    }
    __syncthreads();

    g_sfx[c * (CH + 1) + t] = ssum + soff[w];
    if (t == 0) {
        g_sfx[c * (CH + 1) + CH] = 0.0f;
        if (c == 0) out[0] = 0.0f;            // stream-ordered before rank_loss
    }
}

extern "C" __global__ void __launch_bounds__(2 * RTILE)
rank_loss_kernel(const float* __restrict__ theta, const float* __restrict__ ev,
                 int n, float* __restrict__ out) {
    extern __shared__ unsigned ck[];          // all 64 chunk key tables: 64KB
    __shared__ float shalf[2][RTILE];
    __shared__ float wsum[RTILE / 32];

    const int b = blockIdx.x;
    const int t = threadIdx.x;

    // stage full key table (vectorized: 16 x LDG.128/STS.128 per thread)
    const uint4* src = (const uint4*)g_u;
    uint4*       dst = (uint4*)ck;
    for (int i = t; i < NN / 4; i += 2 * RTILE) dst[i] = src[i];
    __syncthreads();

    const int  sl    = t & (RTILE - 1);       // slot within tile
    const int  half  = t >> 7;                // 0 or 1
    const int  slot  = b * RTILE + sl;
    const int  cbase = half * HCH;            // first chunk for this half
    const unsigned u = ck[slot];

    float rss = 0.0f;
#pragma unroll 1
    for (int cc = 0; cc < HCH; cc += 4) {     // 4 independent search chains
        const unsigned* A0 = ck + (cbase + cc + 0) * CH;
        const unsigned* A1 = ck + (cbase + cc + 1) * CH;
        const unsigned* A2 = ck + (cbase + cc + 2) * CH;
        const unsigned* A3 = ck + (cbase + cc + 3) * CH;
        int l0 = 0, l1 = 0, l2 = 0, l3 = 0;
#pragma unroll
        for (int s = CH / 2; s > 0; s >>= 1) {
            if (A0[l0 + s - 1] < u) l0 += s;
            if (A1[l1 + s - 1] < u) l1 += s;
            if (A2[l2 + s - 1] < u) l2 += s;
            if (A3[l3 + s - 1] < u) l3 += s;
        }
        rss += __ldg(g_sfx + (cbase + cc + 0) * (CH + 1) + l0)
             + __ldg(g_sfx + (cbase + cc + 1) * (CH + 1) + l1)
             + __ldg(g_sfx + (cbase + cc + 2) * (CH + 1) + l2)
             + __ldg(g_sfx + (cbase + cc + 3) * (CH + 1) + l3);
    }
    shalf[half][sl] = rss;
    __syncthreads();

    // threads 0..127: combine halves, compute loss terms, reduce
    float term = 0.0f;
    if (t < RTILE) {
        const float r  = shalf[0][t] + shalf[1][t];
        const int   io = g_idx[b * RTILE + t];
        term = (theta[io] - logf(r)) * ev[io];
    }
    for (int off = 16; off > 0; off >>= 1)
        term += __shfl_down_sync(0xFFFFFFFFu, term, off);
    const int lane = t & 31, w = t >> 5;
    if (lane == 0 && w < RTILE / 32) wsum[w] = term;
    __syncthreads();
    if (t == 0) {
        float s = 0.0f;
#pragma unroll
        for (int ww = 0; ww < RTILE / 32; ww++) s += wsum[ww];
        atomicAdd(out, -s / (float)n);
    }
}

extern "C" void kernel_launch(void* const* d_in, const int* in_sizes, int n_in,
                              void* d_out, int out_size) {
    const float* theta = (const float*)d_in[0];
    const float* T     = (const float*)d_in[1];
    const float* ev    = (const float*)d_in[2];
    float*       out   = (float*)d_out;
    const int n = in_sizes[0];

    static int smem_set = 0;
    const int smem_bytes = NN * (int)sizeof(unsigned);      // 64KB
    if (!smem_set) {
        cudaFuncSetAttribute(rank_loss_kernel,
                             cudaFuncAttributeMaxDynamicSharedMemorySize,
                             smem_bytes);
        smem_set = 1;
    }

    sort_kernel<<<NCH, CH>>>(theta, T, n, out);
    rank_loss_kernel<<<K2G, 2 * RTILE, smem_bytes>>>(theta, ev, n, out);
}